// round 2
// baseline (speedup 1.0000x reference)
#include <cuda_runtime.h>
#include <cuda_bf16.h>

// SAN Subtraction: out[n,c,kk,p] = x[n,c,h,w] - reflectpad(x)[n,c,h+kh,w+kw]
// N=4, C=64, H=W=112, K=7, PAD=3, STRIDE=1, DIL=1, reflect padding.
// out shape (N, C, 49, 12544) fp32 -> 630 MB of mandatory writes: HBM-write bound.
//
// Layout v2: one block = one contiguous (plane, kk) output plane (50 KB).
//  - long monotone store streams per block (DRAM-friendly)
//  - kw fixed per block -> neighbor column reflects hoisted out of the row loop
//  - streaming stores (__stcs): write-once data, evict-first in L2

#define H 112
#define W 112
#define KS 7
#define PADV 3
#define HW (H * W)            // 12544
#define CC 64
#define NN 4

__device__ __forceinline__ int reflect_idx(int j) {
    // numpy 'reflect' (mirror, no edge repeat): j in [-3, 114] -> [0, 111]
    j = j < 0 ? -j : j;
    j = j >= H ? (2 * (H - 1) - j) : j;
    return j;
}

__global__ __launch_bounds__(224) void san_sub_kernel(
    const float* __restrict__ x, float* __restrict__ out)
{
    const int kk    = blockIdx.x;                    // 0..48
    const int plane = blockIdx.z * CC + blockIdx.y;  // n*64 + c
    const int kh    = kk / KS;
    const int kw    = kk - kh * KS;
    const int dh    = kh - PADV;
    const int dw    = kw - PADV;

    const int w4 = threadIdx.x << 2;                 // 0,4,...,108
    const int ty = threadIdx.y;                      // 0..7

    const float* xp = x + (size_t)plane * HW;
    float* op = out + ((size_t)plane * (KS * KS) + kk) * HW;

    // neighbor columns depend only on w and kw -> hoist (with reflect)
    int c0 = reflect_idx(w4 + 0 + dw);
    int c1 = reflect_idx(w4 + 1 + dw);
    int c2 = reflect_idx(w4 + 2 + dw);
    int c3 = reflect_idx(w4 + 3 + dw);

    #pragma unroll
    for (int r0 = 0; r0 < H / 8; ++r0) {            // 14 rows per thread
        const int r  = ty + (r0 << 3);
        const int rh = reflect_idx(r + dh);
        const float* rowc = xp + r * W;
        const float* rown = xp + rh * W;

        const float4 ctr = *reinterpret_cast<const float4*>(rowc + w4);
        float4 o;
        o.x = ctr.x - __ldg(rown + c0);
        o.y = ctr.y - __ldg(rown + c1);
        o.z = ctr.z - __ldg(rown + c2);
        o.w = ctr.w - __ldg(rown + c3);

        __stcs(reinterpret_cast<float4*>(op + r * W + w4), o);
    }
}

extern "C" void kernel_launch(void* const* d_in, const int* in_sizes, int n_in,
                              void* d_out, int out_size) {
    const float* x = (const float*)d_in[0];
    float* out = (float*)d_out;
    dim3 block(28, 8, 1);            // 224 threads: 28 float4 spans x 8 rows
    dim3 grid(KS * KS, CC, NN);      // (49, 64, 4) -> block = one output plane
    san_sub_kernel<<<grid, block>>>(x, out);
}

// round 3
// speedup vs baseline: 1.4337x; 1.4337x over previous
#include <cuda_runtime.h>
#include <cuda_bf16.h>

// SAN Subtraction: out[n,c,kk,p] = x[n,c,h,w] - reflectpad(x)[n,c,h+kh,w+kw]
// N=4, C=64, H=W=112, K=7, PAD=3, reflect. out (N,C,49,12544) fp32 = 630 MB writes.
// HBM-write-bound. v3: linear warp mapping (perfect 512B store coalescing),
// kw-amortized register loads (10 LDG per 7 STG.128), streaming stores,
// occupancy raised via launch_bounds.

#define H 112
#define W 112
#define KS 7
#define PADV 3
#define HW (H * W)            // 12544
#define CC 64
#define NN 4
#define W4N 28                // float4s per row
#define TPB 224               // 7 warps; 224 float4s/block; 14 blocks/plane

__device__ __forceinline__ int reflect_idx(int j) {
    // numpy 'reflect' (mirror, no edge repeat): j in [-3, 114] -> [0, 111]
    j = j < 0 ? -j : j;
    j = j >= H ? (2 * (H - 1) - j) : j;
    return j;
}

__global__ void __launch_bounds__(TPB, 6) san_sub_kernel(
    const float* __restrict__ x, float* __restrict__ out)
{
    const int i  = blockIdx.x * TPB + threadIdx.x;   // float4 index in plane, 0..3135
    const int h  = i / W4N;                          // row (mul-shift)
    const int w4 = (i - h * W4N) << 2;               // 0,4,...,108
    const int plane = blockIdx.z * CC + blockIdx.y;  // n*64 + c

    const float* xp = x + (size_t)plane * HW;
    float* op = out + (size_t)plane * (KS * KS) * HW + (i << 2);

    const float4 ctr = *reinterpret_cast<const float4*>(xp + (i << 2));

    #pragma unroll
    for (int kh = 0; kh < KS; ++kh) {
        const int rh = reflect_idx(h + kh - PADV);
        const float* row = xp + rh * W;

        // 10-wide neighbor span, loaded once, reused by the 7 kw offsets
        float v[10];
        #pragma unroll
        for (int j = 0; j < 10; ++j) {
            const int wi = reflect_idx(w4 - PADV + j);
            v[j] = __ldg(row + wi);
        }

        #pragma unroll
        for (int kw = 0; kw < KS; ++kw) {
            float4 o;
            o.x = ctr.x - v[kw + 0];
            o.y = ctr.y - v[kw + 1];
            o.z = ctr.z - v[kw + 2];
            o.w = ctr.w - v[kw + 3];
            __stcs(reinterpret_cast<float4*>(op + (kh * KS + kw) * HW), o);
        }
    }
}

extern "C" void kernel_launch(void* const* d_in, const int* in_sizes, int n_in,
                              void* d_out, int out_size) {
    const float* x = (const float*)d_in[0];
    float* out = (float*)d_out;
    dim3 block(TPB, 1, 1);
    dim3 grid(HW / 4 / TPB, CC, NN);   // (14, 64, 4)
    san_sub_kernel<<<grid, block>>>(x, out);
}